// round 16
// baseline (speedup 1.0000x reference)
#include <cuda_runtime.h>
#include <cuda_bf16.h>
#include <cuda_fp16.h>
#include <math.h>
#include <stdint.h>

#define NN 40000
#define EE 640000
#define DD 128
#define DEE 64
#define LAMDA 0.5f
#define NEG_SLOPE 0.01f
#define FULL 0xffffffffu

// ---------------- scratch (device globals; zero-initialized at load) --------
__device__ __align__(16) __half g_zh[(size_t)NN * DD];   // z in fp16 (gather payload)
__device__ float g_s[NN];                                // s_node
__device__ float g_d[NN];                                // d_node
__device__ int   g_deg[NN];                              // in-degree histogram (re-zeroed by k_scan)
__device__ int   g_off[NN + 1];                          // CSR offsets
__device__ __align__(16) int g_rank[EE];                 // edge rank within dst group
__device__ __align__(8) uint2 g_pack[EE];                // {src, exp(e)} sorted by dst
__device__ __align__(16) float g_we[DEE];                // edge_fc_w^T @ w_e
__device__ float g_be;                                   // dot(edge_fc_b, w_e)
// packed W fragments, coalesced layout:
//   g_wp[kk*512 + (n>>3)*32 + (n&7)*4 + q] = frag(n, kk, q) = {bh0,bh1,bl0,bl1}
__device__ __align__(16) uint4 g_wp[DD * 32];

// ---------------- helpers ----------------------------------------------------
static __device__ __forceinline__ uint32_t packbf(__nv_bfloat16 a, __nv_bfloat16 b) {
    __nv_bfloat162 p = __halves2bfloat162(a, b);
    return *(uint32_t*)&p;
}

// D(16x8,f32) += A(16x16,bf16,row) * B(16x8,bf16,col)
static __device__ __forceinline__ void mma16816(float* c,
                                                uint32_t a0, uint32_t a1,
                                                uint32_t a2, uint32_t a3,
                                                uint32_t b0, uint32_t b1) {
    asm volatile(
        "mma.sync.aligned.m16n8k16.row.col.f32.bf16.bf16.f32 "
        "{%0,%1,%2,%3}, {%4,%5,%6,%7}, {%8,%9}, {%0,%1,%2,%3};"
        : "+f"(c[0]), "+f"(c[1]), "+f"(c[2]), "+f"(c[3])
        : "r"(a0), "r"(a1), "r"(a2), "r"(a3), "r"(b0), "r"(b1));
}

// ---------------- kernels ---------------------------------------------------

// block 0: projection vectors; blocks 1..16: pack fc_w into bf16 hi/lo frags
__global__ void k_init(const float* __restrict__ fc_w,
                       const float* __restrict__ edge_fc_w,
                       const float* __restrict__ edge_fc_b,
                       const float* __restrict__ attn_w) {
    int b = blockIdx.x, t = threadIdx.x;
    if (b == 0) {
        if (t < DEE) {
            float ee = 0.f;
            for (int j = 0; j < DEE; j++)
                ee += attn_w[2 * DD + j] * edge_fc_w[j * DEE + t];
            g_we[t] = ee;
        }
        if (t == 0) {
            float bb = 0.f;
            for (int j = 0; j < DEE; j++)
                bb += edge_fc_b[j] * attn_w[2 * DD + j];
            g_be = bb;
        }
    } else {
        int idx = (b - 1) * 256 + t;          // 0..4095
        int n = idx >> 5, rem = idx & 31;
        int kk = rem >> 2, q = rem & 3;
        int k0 = kk * 16 + q * 2;
        const float* wr = fc_w + (size_t)n * DD;
        float x0 = wr[k0], x1 = wr[k0 + 1], x8 = wr[k0 + 8], x9 = wr[k0 + 9];
        __nv_bfloat16 h0 = __float2bfloat16(x0), h1 = __float2bfloat16(x1);
        __nv_bfloat16 h8 = __float2bfloat16(x8), h9 = __float2bfloat16(x9);
        uint4 v;
        v.x = packbf(h0, h1);
        v.y = packbf(h8, h9);
        v.z = packbf(__float2bfloat16(x0 - __bfloat162float(h0)),
                     __float2bfloat16(x1 - __bfloat162float(h1)));
        v.w = packbf(__float2bfloat16(x8 - __bfloat162float(h8)),
                     __float2bfloat16(x9 - __bfloat162float(h9)));
        g_wp[kk * 512 + (n >> 3) * 32 + (n & 7) * 4 + q] = v;
    }
}

// in-degree histogram + per-edge rank (atomic return value), int4-vectorized
__global__ void k_hist(const int* __restrict__ dst) {
    int i = blockIdx.x * blockDim.x + threadIdx.x;
    int base = i * 4;
    if (base + 3 < EE) {
        int4 d = *(const int4*)(dst + base);
        int4 r;
        r.x = atomicAdd(&g_deg[d.x], 1);
        r.y = atomicAdd(&g_deg[d.y], 1);
        r.z = atomicAdd(&g_deg[d.z], 1);
        r.w = atomicAdd(&g_deg[d.w], 1);
        *(int4*)(g_rank + base) = r;
    } else {
        for (int j = base; j < EE; j++)
            g_rank[j] = atomicAdd(&g_deg[dst[j]], 1);
    }
}

// single-block exclusive scan of g_deg -> g_off; re-zeroes g_deg.
#define SCAN_T 1024
#define SCAN_C 40
__global__ void k_scan() {
    __shared__ int part[SCAN_T];
    int t = threadIdx.x;
    int base = t * SCAN_C;
    int local[SCAN_C];
    int s = 0;
#pragma unroll
    for (int i = 0; i < SCAN_C; i++) {
        int idx = base + i;
        int v = 0;
        if (idx < NN) {
            v = g_deg[idx];
            g_deg[idx] = 0;
        }
        local[i] = s;
        s += v;
    }
    part[t] = s;
    __syncthreads();
    for (int d = 1; d < SCAN_T; d <<= 1) {
        int v = (t >= d) ? part[t - d] : 0;
        __syncthreads();
        part[t] += v;
        __syncthreads();
    }
    int pre = (t == 0) ? 0 : part[t - 1];
#pragma unroll
    for (int i = 0; i < SCAN_C; i++) {
        int idx = base + i;
        if (idx < NN)
            g_off[idx] = pre + local[i];
    }
    if (t == SCAN_T - 1) g_off[NN] = part[SCAN_T - 1];
}

// ---------------- k_z: HMMA 3xbf16 GEMM, fp16 z output -----------------------
#define SAP 68
#define KZ_SMEM (64 * SAP * 8 + 2 * 4 * 64 * 4)

__global__ void __launch_bounds__(256, 2)
k_z(const float* __restrict__ node_h,
    const float* __restrict__ attn_w) {
    extern __shared__ char smraw[];
    uint2* sA = (uint2*)smraw;                       // [64][SAP]
    float* sRs = (float*)(smraw + 64 * SAP * 8);     // [4 wn][64 rows]
    float* sRd = sRs + 4 * 64;
    int t = threadIdx.x;
    int w = t >> 5, lane = t & 31;
    int q = lane & 3, rr = lane >> 2;
    int wm = w & 1, wn = w >> 1;
    int rowBase = blockIdx.x * 64;

    for (int p = t; p < 64 * 32; p += 256) {
        int row = p >> 5, g = p & 31;
        float4 v = __ldg(&((const float4*)node_h)[(size_t)(rowBase + row) * 32 + g]);
        __nv_bfloat16 h0 = __float2bfloat16(v.x), h1 = __float2bfloat16(v.y);
        __nv_bfloat16 h2 = __float2bfloat16(v.z), h3 = __float2bfloat16(v.w);
        uint2 e0, e1;
        e0.x = packbf(h0, h1);
        e0.y = packbf(__float2bfloat16(v.x - __bfloat162float(h0)),
                      __float2bfloat16(v.y - __bfloat162float(h1)));
        e1.x = packbf(h2, h3);
        e1.y = packbf(__float2bfloat16(v.z - __bfloat162float(h2)),
                      __float2bfloat16(v.w - __bfloat162float(h3)));
        sA[row * SAP + 2 * g] = e0;
        sA[row * SAP + 2 * g + 1] = e1;
    }
    __syncthreads();

    float acch[4][2][4], accl[4][2][4];
#pragma unroll
    for (int nt = 0; nt < 4; nt++)
#pragma unroll
        for (int mt = 0; mt < 2; mt++)
#pragma unroll
            for (int e = 0; e < 4; e++) {
                acch[nt][mt][e] = 0.f;
                accl[nt][mt][e] = 0.f;
            }

#pragma unroll
    for (int kk = 0; kk < 8; kk++) {
        uint4 bb[4];
#pragma unroll
        for (int nt = 0; nt < 4; nt++)
            bb[nt] = __ldg(&g_wp[kk * 512 + (wn * 4 + nt) * 32 + lane]);
        int cp = kk * 8 + q;
#pragma unroll
        for (int mt = 0; mt < 2; mt++) {
            int rm = wm * 32 + mt * 16 + rr;
            uint2 f0 = sA[rm * SAP + cp];
            uint2 f1 = sA[(rm + 8) * SAP + cp];
            uint2 f2 = sA[rm * SAP + cp + 4];
            uint2 f3 = sA[(rm + 8) * SAP + cp + 4];
#pragma unroll
            for (int nt = 0; nt < 4; nt++) {
                mma16816(acch[nt][mt], f0.x, f1.x, f2.x, f3.x, bb[nt].x, bb[nt].y);
                mma16816(accl[nt][mt], f0.y, f1.y, f2.y, f3.y, bb[nt].x, bb[nt].y);
                mma16816(accl[nt][mt], f0.x, f1.x, f2.x, f3.x, bb[nt].z, bb[nt].w);
            }
        }
    }

    float wgt[4][4];
#pragma unroll
    for (int nt = 0; nt < 4; nt++) {
        int c = wn * 32 + nt * 8 + q * 2;
        wgt[nt][0] = __ldg(&attn_w[c]);
        wgt[nt][1] = __ldg(&attn_w[c + 1]);
        wgt[nt][2] = __ldg(&attn_w[DD + c]);
        wgt[nt][3] = __ldg(&attn_w[DD + c + 1]);
    }
#pragma unroll
    for (int mt = 0; mt < 2; mt++) {
        int rloc0 = wm * 32 + mt * 16 + rr;
        int rloc1 = rloc0 + 8;
        int row0 = rowBase + rloc0, row1 = rowBase + rloc1;
        float psl = 0.f, psh = 0.f, pdl = 0.f, pdh = 0.f;
#pragma unroll
        for (int nt = 0; nt < 4; nt++) {
            int c = wn * 32 + nt * 8 + q * 2;
            float c0 = acch[nt][mt][0] + accl[nt][mt][0];
            float c1 = acch[nt][mt][1] + accl[nt][mt][1];
            float c2 = acch[nt][mt][2] + accl[nt][mt][2];
            float c3 = acch[nt][mt][3] + accl[nt][mt][3];
            psl = fmaf(c0, wgt[nt][0], fmaf(c1, wgt[nt][1], psl));
            psh = fmaf(c2, wgt[nt][0], fmaf(c3, wgt[nt][1], psh));
            pdl = fmaf(c0, wgt[nt][2], fmaf(c1, wgt[nt][3], pdl));
            pdh = fmaf(c2, wgt[nt][2], fmaf(c3, wgt[nt][3], pdh));
            *(__half2*)&g_zh[(size_t)row0 * DD + c] = __floats2half2_rn(c0, c1);
            *(__half2*)&g_zh[(size_t)row1 * DD + c] = __floats2half2_rn(c2, c3);
        }
        psl += __shfl_xor_sync(FULL, psl, 1); psl += __shfl_xor_sync(FULL, psl, 2);
        psh += __shfl_xor_sync(FULL, psh, 1); psh += __shfl_xor_sync(FULL, psh, 2);
        pdl += __shfl_xor_sync(FULL, pdl, 1); pdl += __shfl_xor_sync(FULL, pdl, 2);
        pdh += __shfl_xor_sync(FULL, pdh, 1); pdh += __shfl_xor_sync(FULL, pdh, 2);
        if (q == 0) {
            sRs[wn * 64 + rloc0] = psl;
            sRs[wn * 64 + rloc1] = psh;
            sRd[wn * 64 + rloc0] = pdl;
            sRd[wn * 64 + rloc1] = pdh;
        }
    }
    __syncthreads();

    if (t < 64) {
        g_s[rowBase + t] = sRs[t] + sRs[64 + t] + sRs[128 + t] + sRs[192 + t];
    } else if (t < 128) {
        int r = t - 64;
        g_d[rowBase + r] = sRd[r] + sRd[64 + r] + sRd[128 + r] + sRd[192 + r];
    }
}

// edge logits + atomic-free CSR scatter (position = off[d] + rank[i]).
// Stores exp(e) directly (shift-free softmax). 8 lanes/edge, 4 edges/warp.
__global__ void k_edge(const float* __restrict__ edge_h,
                       const int* __restrict__ src,
                       const int* __restrict__ dst) {
    int gw = (blockIdx.x * blockDim.x + threadIdx.x) >> 5;
    int lane = threadIdx.x & 31;
    int sub = lane >> 3;
    int l8 = lane & 7;
    long long ebase = (long long)gw * 4;
    if (ebase >= EE) return;
    int eid = (int)ebase + sub;

    float part = 0.f;
    if (eid < EE) {
        const float4* row = (const float4*)(edge_h + (size_t)eid * DEE);
        float4 v0 = row[l8];
        float4 v1 = row[l8 + 8];
        float4 w0 = ((const float4*)g_we)[l8];
        float4 w1 = ((const float4*)g_we)[l8 + 8];
        part = v0.x * w0.x + v0.y * w0.y + v0.z * w0.z + v0.w * w0.w
             + v1.x * w1.x + v1.y * w1.y + v1.z * w1.z + v1.w * w1.w;
    }
#pragma unroll
    for (int o = 4; o > 0; o >>= 1)
        part += __shfl_xor_sync(FULL, part, o);

    if (l8 == 0 && eid < EE) {
        int s = src[eid], d = dst[eid];
        float v = part + g_be + __ldg(&g_s[s]) + __ldg(&g_d[d]);
        v = (v > 0.f) ? v : NEG_SLOPE * v;
        float ev = __expf(v);
        int p = __ldg(&g_off[d]) + g_rank[eid];
        uint2 pk;
        pk.x = (unsigned)s;
        pk.y = __float_as_uint(ev);
        g_pack[p] = pk;
    }
}

// half-warp per node: pre-exponentiated softmax + fp16-z gather + residual.
// 16 lanes per node; lane owns 8 cols (uint4 = 16B per gathered row).
// ALL intra-loop shuffles use the per-half mask: the two halves serve
// different nodes with different trip counts, so the full-warp mask is UB.
__global__ void k_agg(const float* __restrict__ node_h,
                      float* __restrict__ out) {
    int gw = (blockIdx.x * blockDim.x + threadIdx.x) >> 5;
    int lane = threadIdx.x & 31;
    int hw = lane >> 4, l16 = lane & 15;
    unsigned HMASK = 0xFFFFu << (hw * 16);
    int n = gw * 2 + hw;
    if (n >= NN) return;      // NN even: both halves of a warp exit together

    int beg = g_off[n], end = g_off[n + 1];

    float acc[8];
#pragma unroll
    for (int u = 0; u < 8; u++) acc[u] = 0.f;
    float dsum = 0.f;

    for (int b = beg; b < end; b += 16) {
        int i = b + l16;
        float ev = 0.f;
        int sv = 0;
        if (i < end) {
            uint2 p = g_pack[i];
            sv = (int)p.x;
            ev = __uint_as_float(p.y);
            dsum += ev;
        }
        int cnt = min(16, end - b);
        int j = 0;
        for (; j + 2 <= cnt; j += 2) {
            float ex0 = __shfl_sync(HMASK, ev, hw * 16 + j);
            float ex1 = __shfl_sync(HMASK, ev, hw * 16 + j + 1);
            int s0 = __shfl_sync(HMASK, sv, hw * 16 + j);
            int s1 = __shfl_sync(HMASK, sv, hw * 16 + j + 1);
            uint4 z0 = *((const uint4*)(g_zh + (size_t)s0 * DD) + l16);
            uint4 z1 = *((const uint4*)(g_zh + (size_t)s1 * DD) + l16);
            float2 p0 = __half22float2(*(__half2*)&z0.x);
            float2 p1 = __half22float2(*(__half2*)&z0.y);
            float2 p2 = __half22float2(*(__half2*)&z0.z);
            float2 p3 = __half22float2(*(__half2*)&z0.w);
            float2 q0 = __half22float2(*(__half2*)&z1.x);
            float2 q1 = __half22float2(*(__half2*)&z1.y);
            float2 q2 = __half22float2(*(__half2*)&z1.z);
            float2 q3 = __half22float2(*(__half2*)&z1.w);
            acc[0] = fmaf(ex0, p0.x, fmaf(ex1, q0.x, acc[0]));
            acc[1] = fmaf(ex0, p0.y, fmaf(ex1, q0.y, acc[1]));
            acc[2] = fmaf(ex0, p1.x, fmaf(ex1, q1.x, acc[2]));
            acc[3] = fmaf(ex0, p1.y, fmaf(ex1, q1.y, acc[3]));
            acc[4] = fmaf(ex0, p2.x, fmaf(ex1, q2.x, acc[4]));
            acc[5] = fmaf(ex0, p2.y, fmaf(ex1, q2.y, acc[5]));
            acc[6] = fmaf(ex0, p3.x, fmaf(ex1, q3.x, acc[6]));
            acc[7] = fmaf(ex0, p3.y, fmaf(ex1, q3.y, acc[7]));
        }
        if (j < cnt) {
            float ex = __shfl_sync(HMASK, ev, hw * 16 + j);
            int s = __shfl_sync(HMASK, sv, hw * 16 + j);
            uint4 zv = *((const uint4*)(g_zh + (size_t)s * DD) + l16);
            float2 p0 = __half22float2(*(__half2*)&zv.x);
            float2 p1 = __half22float2(*(__half2*)&zv.y);
            float2 p2 = __half22float2(*(__half2*)&zv.z);
            float2 p3 = __half22float2(*(__half2*)&zv.w);
            acc[0] = fmaf(ex, p0.x, acc[0]);
            acc[1] = fmaf(ex, p0.y, acc[1]);
            acc[2] = fmaf(ex, p1.x, acc[2]);
            acc[3] = fmaf(ex, p1.y, acc[3]);
            acc[4] = fmaf(ex, p2.x, acc[4]);
            acc[5] = fmaf(ex, p2.y, acc[5]);
            acc[6] = fmaf(ex, p3.x, acc[6]);
            acc[7] = fmaf(ex, p3.y, acc[7]);
        }
    }
    // reduce dsum over the 16 lanes of this half-warp
#pragma unroll
    for (int o = 8; o > 0; o >>= 1)
        dsum += __shfl_xor_sync(HMASK, dsum, o);

    float inv = (end > beg) ? (LAMDA / dsum) : 0.f;
    int c0 = l16 * 8;
    const float4* nh = (const float4*)(node_h + (size_t)n * DD + c0);
    float4 nh0 = nh[0], nh1 = nh[1];
    float4 r0, r1;
    r0.x = (1.f - LAMDA) * nh0.x + inv * acc[0];
    r0.y = (1.f - LAMDA) * nh0.y + inv * acc[1];
    r0.z = (1.f - LAMDA) * nh0.z + inv * acc[2];
    r0.w = (1.f - LAMDA) * nh0.w + inv * acc[3];
    r1.x = (1.f - LAMDA) * nh1.x + inv * acc[4];
    r1.y = (1.f - LAMDA) * nh1.y + inv * acc[5];
    r1.z = (1.f - LAMDA) * nh1.z + inv * acc[6];
    r1.w = (1.f - LAMDA) * nh1.w + inv * acc[7];
    float4* op = (float4*)(out + (size_t)n * DD + c0);
    op[0] = r0;
    op[1] = r1;
}

// ---------------- launch -----------------------------------------------------

extern "C" void kernel_launch(void* const* d_in, const int* in_sizes, int n_in,
                              void* d_out, int out_size) {
    const float* node_h    = (const float*)d_in[0];
    const float* edge_h    = (const float*)d_in[1];
    const int*   src       = (const int*)d_in[2];
    const int*   dst       = (const int*)d_in[3];
    const float* fc_w      = (const float*)d_in[4];
    const float* edge_fc_w = (const float*)d_in[5];
    const float* edge_fc_b = (const float*)d_in[6];
    const float* attn_w    = (const float*)d_in[7];
    float* out = (float*)d_out;

    static cudaStream_t s2 = nullptr;
    static cudaEvent_t evF = nullptr, evJ = nullptr;
    if (!s2) {
        cudaFuncSetAttribute(k_z, cudaFuncAttributeMaxDynamicSharedMemorySize, KZ_SMEM);
        cudaStreamCreateWithFlags(&s2, cudaStreamNonBlocking);
        cudaEventCreateWithFlags(&evF, cudaEventDisableTiming);
        cudaEventCreateWithFlags(&evJ, cudaEventDisableTiming);
    }

    // fork: CSR chain (dst only) runs parallel to the GEMM chain
    cudaEventRecord(evF, 0);
    cudaStreamWaitEvent(s2, evF, 0);
    k_hist<<<(EE / 4 + 255) / 256, 256, 0, s2>>>(dst);
    k_scan<<<1, SCAN_T, 0, s2>>>();
    cudaEventRecord(evJ, s2);

    k_init<<<17, 256>>>(fc_w, edge_fc_w, edge_fc_b, attn_w);
    k_z<<<NN / 64, 256, KZ_SMEM>>>(node_h, attn_w);

    // join: k_edge needs g_off/g_rank (s2) + g_s/g_d (k_z) + g_we (k_init)
    cudaStreamWaitEvent(0, evJ, 0);
    k_edge<<<(EE + 31) / 32, 256>>>(edge_h, src, dst);
    // 2 nodes per warp -> NN/2 warps
    k_agg<<<(NN / 2 * 32 + 255) / 256, 256>>>(node_h, out);
}

// round 17
// speedup vs baseline: 1.2824x; 1.2824x over previous
#include <cuda_runtime.h>
#include <cuda_bf16.h>
#include <cuda_fp16.h>
#include <math.h>
#include <stdint.h>

#define NN 40000
#define EE 640000
#define DD 128
#define DEE 64
#define LAMDA 0.5f
#define NEG_SLOPE 0.01f
#define FULL 0xffffffffu

// ---------------- scratch (device globals; zero-initialized at load) --------
__device__ __align__(16) __half g_zh[(size_t)NN * DD];   // z in fp16 (gather payload)
__device__ float g_s[NN];                                // s_node
__device__ float g_d[NN];                                // d_node
__device__ int   g_deg[NN];                              // in-degree histogram (re-zeroed by k_scan)
__device__ int   g_off[NN + 1];                          // CSR offsets
__device__ __align__(16) int g_rank[EE];                 // edge rank within dst group
__device__ __align__(8) uint2 g_pack[EE];                // {src, exp(e)} sorted by dst
__device__ __align__(16) float g_we[DEE];                // edge_fc_w^T @ w_e
__device__ float g_be;                                   // dot(edge_fc_b, w_e)
// packed W fragments, coalesced layout:
//   g_wp[kk*512 + (n>>3)*32 + (n&7)*4 + q] = frag(n, kk, q) = {bh0,bh1,bl0,bl1}
__device__ __align__(16) uint4 g_wp[DD * 32];

// ---------------- helpers ----------------------------------------------------
static __device__ __forceinline__ uint32_t packbf(__nv_bfloat16 a, __nv_bfloat16 b) {
    __nv_bfloat162 p = __halves2bfloat162(a, b);
    return *(uint32_t*)&p;
}

// D(16x8,f32) += A(16x16,bf16,row) * B(16x8,bf16,col)
static __device__ __forceinline__ void mma16816(float* c,
                                                uint32_t a0, uint32_t a1,
                                                uint32_t a2, uint32_t a3,
                                                uint32_t b0, uint32_t b1) {
    asm volatile(
        "mma.sync.aligned.m16n8k16.row.col.f32.bf16.bf16.f32 "
        "{%0,%1,%2,%3}, {%4,%5,%6,%7}, {%8,%9}, {%0,%1,%2,%3};"
        : "+f"(c[0]), "+f"(c[1]), "+f"(c[2]), "+f"(c[3])
        : "r"(a0), "r"(a1), "r"(a2), "r"(a3), "r"(b0), "r"(b1));
}

// ---------------- kernels ---------------------------------------------------

// block 0: projection vectors; blocks 1..16: pack fc_w into bf16 hi/lo frags
__global__ void k_init(const float* __restrict__ fc_w,
                       const float* __restrict__ edge_fc_w,
                       const float* __restrict__ edge_fc_b,
                       const float* __restrict__ attn_w) {
    int b = blockIdx.x, t = threadIdx.x;
    if (b == 0) {
        if (t < DEE) {
            float ee = 0.f;
            for (int j = 0; j < DEE; j++)
                ee += attn_w[2 * DD + j] * edge_fc_w[j * DEE + t];
            g_we[t] = ee;
        }
        if (t == 0) {
            float bb = 0.f;
            for (int j = 0; j < DEE; j++)
                bb += edge_fc_b[j] * attn_w[2 * DD + j];
            g_be = bb;
        }
    } else {
        int idx = (b - 1) * 256 + t;          // 0..4095
        int n = idx >> 5, rem = idx & 31;
        int kk = rem >> 2, q = rem & 3;
        int k0 = kk * 16 + q * 2;
        const float* wr = fc_w + (size_t)n * DD;
        float x0 = wr[k0], x1 = wr[k0 + 1], x8 = wr[k0 + 8], x9 = wr[k0 + 9];
        __nv_bfloat16 h0 = __float2bfloat16(x0), h1 = __float2bfloat16(x1);
        __nv_bfloat16 h8 = __float2bfloat16(x8), h9 = __float2bfloat16(x9);
        uint4 v;
        v.x = packbf(h0, h1);
        v.y = packbf(h8, h9);
        v.z = packbf(__float2bfloat16(x0 - __bfloat162float(h0)),
                     __float2bfloat16(x1 - __bfloat162float(h1)));
        v.w = packbf(__float2bfloat16(x8 - __bfloat162float(h8)),
                     __float2bfloat16(x9 - __bfloat162float(h9)));
        g_wp[kk * 512 + (n >> 3) * 32 + (n & 7) * 4 + q] = v;
    }
}

// in-degree histogram + per-edge rank (atomic return value), int4-vectorized
__global__ void k_hist(const int* __restrict__ dst) {
    int i = blockIdx.x * blockDim.x + threadIdx.x;
    int base = i * 4;
    if (base + 3 < EE) {
        int4 d = *(const int4*)(dst + base);
        int4 r;
        r.x = atomicAdd(&g_deg[d.x], 1);
        r.y = atomicAdd(&g_deg[d.y], 1);
        r.z = atomicAdd(&g_deg[d.z], 1);
        r.w = atomicAdd(&g_deg[d.w], 1);
        *(int4*)(g_rank + base) = r;
    } else {
        for (int j = base; j < EE; j++)
            g_rank[j] = atomicAdd(&g_deg[dst[j]], 1);
    }
}

// single-block exclusive scan, smem-staged for fully coalesced global access.
// Per-thread chunk stored at stride 41 (41*9 mod 32 covers all banks -> the
// serial chunk scan is bank-conflict-free).
#define SCAN_T 1024
#define SCAN_C 40
#define SCAN_N (SCAN_T * SCAN_C)          // 40960 >= NN
#define SCAN_CP 41
#define KSCAN_SMEM ((SCAN_T * SCAN_CP + SCAN_T) * 4)

__global__ void k_scan() {
    extern __shared__ int sd[];           // [SCAN_T*SCAN_CP] data, [SCAN_T] partials
    int* part = sd + SCAN_T * SCAN_CP;
    int t = threadIdx.x;

    // coalesced load g_deg -> padded smem; zero g_deg for the next call
    for (int j = t; j < SCAN_N; j += SCAN_T) {
        int v = 0;
        if (j < NN) { v = g_deg[j]; g_deg[j] = 0; }
        sd[(j / SCAN_C) * SCAN_CP + (j % SCAN_C)] = v;
    }
    __syncthreads();

    // per-thread serial exclusive scan of its chunk (conflict-free)
    int base = t * SCAN_CP;
    int s = 0;
#pragma unroll
    for (int i = 0; i < SCAN_C; i++) {
        int v = sd[base + i];
        sd[base + i] = s;
        s += v;
    }
    part[t] = s;
    __syncthreads();

    // block scan over 1024 partials
    for (int d = 1; d < SCAN_T; d <<= 1) {
        int v = (t >= d) ? part[t - d] : 0;
        __syncthreads();
        part[t] += v;
        __syncthreads();
    }
    int pre = (t == 0) ? 0 : part[t - 1];
#pragma unroll
    for (int i = 0; i < SCAN_C; i++)
        sd[base + i] += pre;
    __syncthreads();

    // coalesced store -> g_off
    for (int j = t; j < SCAN_N; j += SCAN_T) {
        if (j < NN)
            g_off[j] = sd[(j / SCAN_C) * SCAN_CP + (j % SCAN_C)];
    }
    if (t == SCAN_T - 1) g_off[NN] = part[SCAN_T - 1];
}

// ---------------- k_z: HMMA 3xbf16 GEMM, fp16 z output -----------------------
#define SAP 68
#define KZ_SMEM (64 * SAP * 8 + 2 * 4 * 64 * 4)

__global__ void __launch_bounds__(256, 2)
k_z(const float* __restrict__ node_h,
    const float* __restrict__ attn_w) {
    extern __shared__ char smraw[];
    uint2* sA = (uint2*)smraw;                       // [64][SAP]
    float* sRs = (float*)(smraw + 64 * SAP * 8);     // [4 wn][64 rows]
    float* sRd = sRs + 4 * 64;
    int t = threadIdx.x;
    int w = t >> 5, lane = t & 31;
    int q = lane & 3, rr = lane >> 2;
    int wm = w & 1, wn = w >> 1;
    int rowBase = blockIdx.x * 64;

    for (int p = t; p < 64 * 32; p += 256) {
        int row = p >> 5, g = p & 31;
        float4 v = __ldg(&((const float4*)node_h)[(size_t)(rowBase + row) * 32 + g]);
        __nv_bfloat16 h0 = __float2bfloat16(v.x), h1 = __float2bfloat16(v.y);
        __nv_bfloat16 h2 = __float2bfloat16(v.z), h3 = __float2bfloat16(v.w);
        uint2 e0, e1;
        e0.x = packbf(h0, h1);
        e0.y = packbf(__float2bfloat16(v.x - __bfloat162float(h0)),
                      __float2bfloat16(v.y - __bfloat162float(h1)));
        e1.x = packbf(h2, h3);
        e1.y = packbf(__float2bfloat16(v.z - __bfloat162float(h2)),
                      __float2bfloat16(v.w - __bfloat162float(h3)));
        sA[row * SAP + 2 * g] = e0;
        sA[row * SAP + 2 * g + 1] = e1;
    }
    __syncthreads();

    float acch[4][2][4], accl[4][2][4];
#pragma unroll
    for (int nt = 0; nt < 4; nt++)
#pragma unroll
        for (int mt = 0; mt < 2; mt++)
#pragma unroll
            for (int e = 0; e < 4; e++) {
                acch[nt][mt][e] = 0.f;
                accl[nt][mt][e] = 0.f;
            }

#pragma unroll
    for (int kk = 0; kk < 8; kk++) {
        uint4 bb[4];
#pragma unroll
        for (int nt = 0; nt < 4; nt++)
            bb[nt] = __ldg(&g_wp[kk * 512 + (wn * 4 + nt) * 32 + lane]);
        int cp = kk * 8 + q;
#pragma unroll
        for (int mt = 0; mt < 2; mt++) {
            int rm = wm * 32 + mt * 16 + rr;
            uint2 f0 = sA[rm * SAP + cp];
            uint2 f1 = sA[(rm + 8) * SAP + cp];
            uint2 f2 = sA[rm * SAP + cp + 4];
            uint2 f3 = sA[(rm + 8) * SAP + cp + 4];
#pragma unroll
            for (int nt = 0; nt < 4; nt++) {
                mma16816(acch[nt][mt], f0.x, f1.x, f2.x, f3.x, bb[nt].x, bb[nt].y);
                mma16816(accl[nt][mt], f0.y, f1.y, f2.y, f3.y, bb[nt].x, bb[nt].y);
                mma16816(accl[nt][mt], f0.x, f1.x, f2.x, f3.x, bb[nt].z, bb[nt].w);
            }
        }
    }

    float wgt[4][4];
#pragma unroll
    for (int nt = 0; nt < 4; nt++) {
        int c = wn * 32 + nt * 8 + q * 2;
        wgt[nt][0] = __ldg(&attn_w[c]);
        wgt[nt][1] = __ldg(&attn_w[c + 1]);
        wgt[nt][2] = __ldg(&attn_w[DD + c]);
        wgt[nt][3] = __ldg(&attn_w[DD + c + 1]);
    }
#pragma unroll
    for (int mt = 0; mt < 2; mt++) {
        int rloc0 = wm * 32 + mt * 16 + rr;
        int rloc1 = rloc0 + 8;
        int row0 = rowBase + rloc0, row1 = rowBase + rloc1;
        float psl = 0.f, psh = 0.f, pdl = 0.f, pdh = 0.f;
#pragma unroll
        for (int nt = 0; nt < 4; nt++) {
            int c = wn * 32 + nt * 8 + q * 2;
            float c0 = acch[nt][mt][0] + accl[nt][mt][0];
            float c1 = acch[nt][mt][1] + accl[nt][mt][1];
            float c2 = acch[nt][mt][2] + accl[nt][mt][2];
            float c3 = acch[nt][mt][3] + accl[nt][mt][3];
            psl = fmaf(c0, wgt[nt][0], fmaf(c1, wgt[nt][1], psl));
            psh = fmaf(c2, wgt[nt][0], fmaf(c3, wgt[nt][1], psh));
            pdl = fmaf(c0, wgt[nt][2], fmaf(c1, wgt[nt][3], pdl));
            pdh = fmaf(c2, wgt[nt][2], fmaf(c3, wgt[nt][3], pdh));
            *(__half2*)&g_zh[(size_t)row0 * DD + c] = __floats2half2_rn(c0, c1);
            *(__half2*)&g_zh[(size_t)row1 * DD + c] = __floats2half2_rn(c2, c3);
        }
        psl += __shfl_xor_sync(FULL, psl, 1); psl += __shfl_xor_sync(FULL, psl, 2);
        psh += __shfl_xor_sync(FULL, psh, 1); psh += __shfl_xor_sync(FULL, psh, 2);
        pdl += __shfl_xor_sync(FULL, pdl, 1); pdl += __shfl_xor_sync(FULL, pdl, 2);
        pdh += __shfl_xor_sync(FULL, pdh, 1); pdh += __shfl_xor_sync(FULL, pdh, 2);
        if (q == 0) {
            sRs[wn * 64 + rloc0] = psl;
            sRs[wn * 64 + rloc1] = psh;
            sRd[wn * 64 + rloc0] = pdl;
            sRd[wn * 64 + rloc1] = pdh;
        }
    }
    __syncthreads();

    if (t < 64) {
        g_s[rowBase + t] = sRs[t] + sRs[64 + t] + sRs[128 + t] + sRs[192 + t];
    } else if (t < 128) {
        int r = t - 64;
        g_d[rowBase + r] = sRd[r] + sRd[64 + r] + sRd[128 + r] + sRd[192 + r];
    }
}

// edge logits + atomic-free CSR scatter (position = off[d] + rank[i]).
// Stores exp(e) directly (shift-free softmax). 8 lanes/edge, 4 edges/warp.
__global__ void k_edge(const float* __restrict__ edge_h,
                       const int* __restrict__ src,
                       const int* __restrict__ dst) {
    int gw = (blockIdx.x * blockDim.x + threadIdx.x) >> 5;
    int lane = threadIdx.x & 31;
    int sub = lane >> 3;
    int l8 = lane & 7;
    long long ebase = (long long)gw * 4;
    if (ebase >= EE) return;
    int eid = (int)ebase + sub;

    float part = 0.f;
    if (eid < EE) {
        const float4* row = (const float4*)(edge_h + (size_t)eid * DEE);
        float4 v0 = row[l8];
        float4 v1 = row[l8 + 8];
        float4 w0 = ((const float4*)g_we)[l8];
        float4 w1 = ((const float4*)g_we)[l8 + 8];
        part = v0.x * w0.x + v0.y * w0.y + v0.z * w0.z + v0.w * w0.w
             + v1.x * w1.x + v1.y * w1.y + v1.z * w1.z + v1.w * w1.w;
    }
#pragma unroll
    for (int o = 4; o > 0; o >>= 1)
        part += __shfl_xor_sync(FULL, part, o);

    if (l8 == 0 && eid < EE) {
        int s = src[eid], d = dst[eid];
        float v = part + g_be + __ldg(&g_s[s]) + __ldg(&g_d[d]);
        v = (v > 0.f) ? v : NEG_SLOPE * v;
        float ev = __expf(v);
        int p = __ldg(&g_off[d]) + g_rank[eid];
        uint2 pk;
        pk.x = (unsigned)s;
        pk.y = __float_as_uint(ev);
        g_pack[p] = pk;
    }
}

// warp per node: pre-exponentiated softmax + weighted fp16-z gather + residual.
// Lane owns 4 cols (8B uint2 per row); 4 rows in flight per step.
__global__ void k_agg(const float* __restrict__ node_h,
                      float* __restrict__ out) {
    int n = (blockIdx.x * blockDim.x + threadIdx.x) >> 5;
    int lane = threadIdx.x & 31;
    if (n >= NN) return;

    int beg = g_off[n], end = g_off[n + 1];

    float acc0 = 0.f, acc1 = 0.f, acc2 = 0.f, acc3 = 0.f;
    float dsum = 0.f;
    for (int b = beg; b < end; b += 32) {
        int i = b + lane;
        float ev = 0.f;
        int sv = 0;
        if (i < end) {
            uint2 p = g_pack[i];
            sv = (int)p.x;
            ev = __uint_as_float(p.y);
            dsum += ev;
        }
        int cnt = min(32, end - b);
        int j = 0;
        for (; j + 4 <= cnt; j += 4) {
            float ex0 = __shfl_sync(FULL, ev, j);
            float ex1 = __shfl_sync(FULL, ev, j + 1);
            float ex2 = __shfl_sync(FULL, ev, j + 2);
            float ex3 = __shfl_sync(FULL, ev, j + 3);
            int s0 = __shfl_sync(FULL, sv, j);
            int s1 = __shfl_sync(FULL, sv, j + 1);
            int s2 = __shfl_sync(FULL, sv, j + 2);
            int s3 = __shfl_sync(FULL, sv, j + 3);
            uint2 z0 = *((const uint2*)(g_zh + (size_t)s0 * DD) + lane);
            uint2 z1 = *((const uint2*)(g_zh + (size_t)s1 * DD) + lane);
            uint2 z2 = *((const uint2*)(g_zh + (size_t)s2 * DD) + lane);
            uint2 z3 = *((const uint2*)(g_zh + (size_t)s3 * DD) + lane);
            float2 a0 = __half22float2(*(__half2*)&z0.x);
            float2 b0 = __half22float2(*(__half2*)&z0.y);
            float2 a1 = __half22float2(*(__half2*)&z1.x);
            float2 b1 = __half22float2(*(__half2*)&z1.y);
            float2 a2 = __half22float2(*(__half2*)&z2.x);
            float2 b2 = __half22float2(*(__half2*)&z2.y);
            float2 a3 = __half22float2(*(__half2*)&z3.x);
            float2 b3 = __half22float2(*(__half2*)&z3.y);
            acc0 = fmaf(ex0, a0.x, fmaf(ex1, a1.x, fmaf(ex2, a2.x, fmaf(ex3, a3.x, acc0))));
            acc1 = fmaf(ex0, a0.y, fmaf(ex1, a1.y, fmaf(ex2, a2.y, fmaf(ex3, a3.y, acc1))));
            acc2 = fmaf(ex0, b0.x, fmaf(ex1, b1.x, fmaf(ex2, b2.x, fmaf(ex3, b3.x, acc2))));
            acc3 = fmaf(ex0, b0.y, fmaf(ex1, b1.y, fmaf(ex2, b2.y, fmaf(ex3, b3.y, acc3))));
        }
        for (; j < cnt; j++) {
            float ex = __shfl_sync(FULL, ev, j);
            int s = __shfl_sync(FULL, sv, j);
            uint2 zv = *((const uint2*)(g_zh + (size_t)s * DD) + lane);
            float2 a = __half22float2(*(__half2*)&zv.x);
            float2 bq = __half22float2(*(__half2*)&zv.y);
            acc0 = fmaf(ex, a.x, acc0);
            acc1 = fmaf(ex, a.y, acc1);
            acc2 = fmaf(ex, bq.x, acc2);
            acc3 = fmaf(ex, bq.y, acc3);
        }
    }
#pragma unroll
    for (int o = 16; o > 0; o >>= 1)
        dsum += __shfl_xor_sync(FULL, dsum, o);

    float inv = (end > beg) ? (LAMDA / dsum) : 0.f;
    float4 nh = ((const float4*)(node_h + (size_t)n * DD))[lane];
    float4 r;
    r.x = (1.f - LAMDA) * nh.x + inv * acc0;
    r.y = (1.f - LAMDA) * nh.y + inv * acc1;
    r.z = (1.f - LAMDA) * nh.z + inv * acc2;
    r.w = (1.f - LAMDA) * nh.w + inv * acc3;
    ((float4*)(out + (size_t)n * DD))[lane] = r;
}

// ---------------- launch -----------------------------------------------------

extern "C" void kernel_launch(void* const* d_in, const int* in_sizes, int n_in,
                              void* d_out, int out_size) {
    const float* node_h    = (const float*)d_in[0];
    const float* edge_h    = (const float*)d_in[1];
    const int*   src       = (const int*)d_in[2];
    const int*   dst       = (const int*)d_in[3];
    const float* fc_w      = (const float*)d_in[4];
    const float* edge_fc_w = (const float*)d_in[5];
    const float* edge_fc_b = (const float*)d_in[6];
    const float* attn_w    = (const float*)d_in[7];
    float* out = (float*)d_out;

    static cudaStream_t s2 = nullptr;
    static cudaEvent_t evF = nullptr, evJ = nullptr;
    if (!s2) {
        cudaFuncSetAttribute(k_z, cudaFuncAttributeMaxDynamicSharedMemorySize, KZ_SMEM);
        cudaFuncSetAttribute(k_scan, cudaFuncAttributeMaxDynamicSharedMemorySize, KSCAN_SMEM);
        cudaStreamCreateWithFlags(&s2, cudaStreamNonBlocking);
        cudaEventCreateWithFlags(&evF, cudaEventDisableTiming);
        cudaEventCreateWithFlags(&evJ, cudaEventDisableTiming);
    }

    // fork: CSR chain (dst only) runs parallel to the GEMM chain
    cudaEventRecord(evF, 0);
    cudaStreamWaitEvent(s2, evF, 0);
    k_hist<<<(EE / 4 + 255) / 256, 256, 0, s2>>>(dst);
    k_scan<<<1, SCAN_T, KSCAN_SMEM, s2>>>();
    cudaEventRecord(evJ, s2);

    k_init<<<17, 256>>>(fc_w, edge_fc_w, edge_fc_b, attn_w);
    k_z<<<NN / 64, 256, KZ_SMEM>>>(node_h, attn_w);

    // join: k_edge needs g_off/g_rank (s2) + g_s/g_d (k_z) + g_we (k_init)
    cudaStreamWaitEvent(0, evJ, 0);
    k_edge<<<(EE + 31) / 32, 256>>>(edge_h, src, dst);
    k_agg<<<(NN * 32 + 255) / 256, 256>>>(node_h, out);
}